// round 11
// baseline (speedup 1.0000x reference)
#include <cuda_runtime.h>
#include <cuda_fp16.h>

typedef unsigned int u32;

#define BB 8
#define CC 512
#define TT 4096
#define SCALE_F 0.125f
#define NELEM ((size_t)BB * CC * TT)
#define CCSQ ((size_t)CC * CC)
#define KSPL_G 4

// ---------------- scratch ----------------
__device__ half g_x_h[NELEM];
__device__ half g_x_l[NELEM];
__device__ half g_wq_h[CCSQ];
__device__ half g_wq_l[CCSQ];
__device__ half g_wk_h[CCSQ];
__device__ half g_wk_l[CCSQ];
__device__ half g_wv_h[CCSQ];
__device__ half g_wv_l[CCSQ];
__device__ float g_part[(size_t)KSPL_G * BB * CCSQ];
__device__ half g_G_h[(size_t)BB * CCSQ];
__device__ half g_G_l[(size_t)BB * CCSQ];
__device__ half g_t2_h[(size_t)BB * CCSQ];
__device__ half g_t2_l[(size_t)BB * CCSQ];
__device__ float g_dots[(size_t)BB * CCSQ];
__device__ half g_a_h[(size_t)BB * CCSQ];
__device__ half g_a_l[(size_t)BB * CCSQ];
__device__ half g_P_h[(size_t)BB * CCSQ];
__device__ half g_P_l[(size_t)BB * CCSQ];
__device__ float g_sx[BB * CC];
__device__ float g_w1[BB * CC];
__device__ float g_w2[BB * CC];
__device__ float g_pb[BB * CC];

// upper-triangle maps: 128x128 subtiles (gcombine + BM=128 TRI)
__device__ __constant__ int c_ti[10] = {0, 0, 0, 0, 1, 1, 1, 2, 2, 3};
__device__ __constant__ int c_tj[10] = {0, 1, 2, 3, 1, 2, 3, 2, 3, 3};
// 256x128 blocks covering the upper triangle (BM=256 TRI): 6 blocks
__device__ __constant__ int c_bi2[6] = {0, 0, 0, 0, 1, 1};
__device__ __constant__ int c_bj2[6] = {0, 1, 2, 3, 2, 3};

// ---------------- helpers ----------------
__device__ __forceinline__ u32 smem_u32(const void* p) {
    u32 a;
    asm("{ .reg .u64 t; cvta.to.shared.u64 t, %1; cvt.u32.u64 %0, t; }" : "=r"(a) : "l"(p));
    return a;
}
__device__ __forceinline__ void split2h(float a, float b, u32& h, u32& l) {
    __half h0 = __float2half_rn(a), h1 = __float2half_rn(b);
    __half l0 = __float2half_rn(a - __half2float(h0));
    __half l1 = __float2half_rn(b - __half2float(h1));
    __half2 hh = __halves2half2(h0, h1), ll = __halves2half2(l0, l1);
    h = *(u32*)&hh;
    l = *(u32*)&ll;
}
__device__ __forceinline__ void ldsm4(u32& r0, u32& r1, u32& r2, u32& r3, u32 addr) {
    asm volatile("ldmatrix.sync.aligned.m8n8.x4.shared.b16 {%0,%1,%2,%3}, [%4];"
                 : "=r"(r0), "=r"(r1), "=r"(r2), "=r"(r3) : "r"(addr));
}
__device__ __forceinline__ void ldsm4t(u32& r0, u32& r1, u32& r2, u32& r3, u32 addr) {
    asm volatile("ldmatrix.sync.aligned.m8n8.x4.trans.shared.b16 {%0,%1,%2,%3}, [%4];"
                 : "=r"(r0), "=r"(r1), "=r"(r2), "=r"(r3) : "r"(addr));
}
__device__ __forceinline__ void mma16816(float* d, const u32* a, u32 b0, u32 b1) {
    asm volatile(
        "mma.sync.aligned.m16n8k16.row.col.f32.f16.f16.f32 "
        "{%0,%1,%2,%3}, {%4,%5,%6,%7}, {%8,%9}, {%0,%1,%2,%3};"
        : "+f"(d[0]), "+f"(d[1]), "+f"(d[2]), "+f"(d[3])
        : "r"(a[0]), "r"(a[1]), "r"(a[2]), "r"(a[3]), "r"(b0), "r"(b1));
}
// cp.async ROWS x 64 half (128B rows), SW swizzle; NTH threads.
template <int ROWS, int NTH>
__device__ __forceinline__ void cp_tileA(u32 sdst, const half* g, int ld, int tid) {
    const int seg = tid & 7;
    const int r0 = tid >> 3;            // 0..NTH/8-1
    constexpr int RP = NTH / 8;
    const char* gc = (const char*)g + seg * 16;
#pragma unroll
    for (int p = 0; p < ROWS / RP; p++) {
        int row = p * RP + r0;
        u32 dst = sdst + row * 128 + ((seg ^ (row & 7)) << 4);
        const void* src = gc + (size_t)row * ld * sizeof(half);
        asm volatile("cp.async.cg.shared.global [%0], [%1], 16;" :: "r"(dst), "l"(src) : "memory");
    }
}
// cp.async 64 rows x 128 half (256B rows); NTH threads.
template <int NTH>
__device__ __forceinline__ void cp_tileB(u32 sdst, const half* g, int ld, int tid) {
    const int seg = tid & 15;
    const int r0 = tid >> 4;            // 0..NTH/16-1
    constexpr int RP = NTH / 16;
    const char* gc = (const char*)g + seg * 16;
#pragma unroll
    for (int p = 0; p < 64 / RP; p++) {
        int row = p * RP + r0;
        u32 dst = sdst + row * 256 + ((seg ^ (row & 7)) << 4);
        const void* src = gc + (size_t)row * ld * sizeof(half);
        asm volatile("cp.async.cg.shared.global [%0], [%1], 16;" :: "r"(dst), "l"(src) : "memory");
    }
}

// ---------------------------------------------------------------------------
// GEMM D[m,n] = scale*(A.B) + bias; fp16 2-term split.
// BM in {128, 256}; BN=128; BK=64; threads = 2*BM (warp tile 32x64 always).
// NPROD=3: AhBh+AlBh+AhBl. NPROD=2: AhBh+AlBh (Bl never loaded).
// BTRANS: B is [k][n] n-contig via ldmatrix.trans. TRI: triangular G grids.
// ---------------------------------------------------------------------------
template <int BM, bool BIASROW, bool SPLIT, int KSPL, bool TRI, bool BTRANS, int NPROD>
__global__ __launch_bounds__(BM * 2) void gemm_mma(
    const half* __restrict__ Ah, const half* __restrict__ Al, size_t sA, int lda,
    const half* __restrict__ Bh, const half* __restrict__ Bl, size_t sB, int ldb,
    float* __restrict__ C, half* __restrict__ Ch, half* __restrict__ Cl,
    size_t sC, int ldc, const float* __restrict__ bias, int biasZ,
    float scale, int K)
{
    constexpr int NTH = BM * 2;
    constexpr int MW = BM / 32;                     // m-warps (x2 n-warps)
    constexpr u32 A_B = BM * 128;                   // bytes of one A tile
    constexpr u32 STAGE = 2 * A_B + ((NPROD == 3) ? 32768 : 16384);

    extern __shared__ char dyn[];
    char* dg = (char*)(((size_t)dyn + 1023) & ~(size_t)1023);
    const u32 base = smem_u32(dg);

    const int tid = threadIdx.x, wid = tid >> 5, lane = tid & 31;
    const int z = blockIdx.z;
    const int batch = z / KSPL, ksl = z - batch * KSPL;
    int m0, n0;
    if (TRI) {
        if (BM == 256) { m0 = c_bi2[blockIdx.x] * 256; n0 = c_bj2[blockIdx.x] * 128; }
        else           { m0 = c_ti[blockIdx.x] * 128;  n0 = c_tj[blockIdx.x] * 128; }
    } else {
        m0 = blockIdx.y * BM; n0 = blockIdx.x * 128;
    }
    const int wm = wid % MW, wn = wid / MW;

    const half* pAh = Ah + (size_t)batch * sA + (size_t)ksl * K + (size_t)m0 * lda;
    const half* pAl = Al + (size_t)batch * sA + (size_t)ksl * K + (size_t)m0 * lda;
    const half* pBh;
    const half* pBl;
    if (BTRANS) {
        pBh = Bh + (size_t)batch * sB + (size_t)(ksl * K) * ldb + n0;
        pBl = Bl + (size_t)batch * sB + (size_t)(ksl * K) * ldb + n0;
    } else {
        pBh = Bh + (size_t)batch * sB + (size_t)ksl * K + (size_t)n0 * ldb;
        pBl = Bl + (size_t)batch * sB + (size_t)ksl * K + (size_t)n0 * ldb;
    }

    const int NCH = K >> 6;

    float acc[2][8][4];
#pragma unroll
    for (int i = 0; i < 2; i++)
#pragma unroll
        for (int j = 0; j < 8; j++)
#pragma unroll
            for (int t = 0; t < 4; t++) acc[i][j][t] = 0.0f;

    // prologue
    cp_tileA<BM, NTH>(base, pAh, lda, tid);
    cp_tileA<BM, NTH>(base + A_B, pAl, lda, tid);
    if (BTRANS) {
        cp_tileB<NTH>(base + 2 * A_B, pBh, ldb, tid);
        if (NPROD == 3) cp_tileB<NTH>(base + 2 * A_B + 16384, pBl, ldb, tid);
    } else {
        cp_tileA<128, NTH>(base + 2 * A_B, pBh, ldb, tid);
        if (NPROD == 3) cp_tileA<128, NTH>(base + 2 * A_B + 16384, pBl, ldb, tid);
    }
    asm volatile("cp.async.commit_group;" ::: "memory");

    for (int c = 0; c < NCH; c++) {
        const int st = c & 1;
        if (c + 1 < NCH) {
            const u32 sb = base + (st ^ 1) * STAGE;
            const int ko = (c + 1) * 64;
            cp_tileA<BM, NTH>(sb, pAh + ko, lda, tid);
            cp_tileA<BM, NTH>(sb + A_B, pAl + ko, lda, tid);
            if (BTRANS) {
                cp_tileB<NTH>(sb + 2 * A_B, pBh + (size_t)ko * ldb, ldb, tid);
                if (NPROD == 3) cp_tileB<NTH>(sb + 2 * A_B + 16384, pBl + (size_t)ko * ldb, ldb, tid);
            } else {
                cp_tileA<128, NTH>(sb + 2 * A_B, pBh + ko, ldb, tid);
                if (NPROD == 3) cp_tileA<128, NTH>(sb + 2 * A_B + 16384, pBl + ko, ldb, tid);
            }
        }
        asm volatile("cp.async.commit_group;" ::: "memory");
        asm volatile("cp.async.wait_group 1;" ::: "memory");
        __syncthreads();

        const u32 sAh = base + st * STAGE;
        const u32 sAl = sAh + A_B, sBh = sAh + 2 * A_B, sBl = sAh + 2 * A_B + 16384;

#pragma unroll
        for (int ks = 0; ks < 4; ks++) {
            u32 ah[2][4], al[2][4];
#pragma unroll
            for (int mi = 0; mi < 2; mi++) {
                const int row = wm * 32 + mi * 16 + (lane & 15);
                const u32 off = row * 128 + ((((ks << 1) | (lane >> 4)) ^ (row & 7)) << 4);
                ldsm4(ah[mi][0], ah[mi][1], ah[mi][2], ah[mi][3], sAh + off);
                ldsm4(al[mi][0], al[mi][1], al[mi][2], al[mi][3], sAl + off);
            }
            u32 bh[4][4], bl[4][4];
#pragma unroll
            for (int ni = 0; ni < 4; ni++) {
                if (BTRANS) {
                    const int row = ks * 16 + (lane & 15);
                    const int chunk = wn * 8 + ni * 2 + (lane >> 4);
                    const u32 off = row * 256 + ((chunk ^ (row & 7)) << 4);
                    ldsm4t(bh[ni][0], bh[ni][1], bh[ni][2], bh[ni][3], sBh + off);
                    if (NPROD == 3) ldsm4t(bl[ni][0], bl[ni][1], bl[ni][2], bl[ni][3], sBl + off);
                } else {
                    const int row = wn * 64 + ni * 16 + (lane & 15);
                    const u32 off = row * 128 + ((((ks << 1) | (lane >> 4)) ^ (row & 7)) << 4);
                    ldsm4(bh[ni][0], bh[ni][1], bh[ni][2], bh[ni][3], sBh + off);
                    if (NPROD == 3) ldsm4(bl[ni][0], bl[ni][1], bl[ni][2], bl[ni][3], sBl + off);
                }
            }
            const int p0 = BTRANS ? 1 : 2;   // k-hi fragment index
            const int q0 = BTRANS ? 2 : 1;   // n+8 fragment base
#pragma unroll
            for (int p = 0; p < NPROD; p++) {
                u32 (*af)[4] = (p == 1) ? al : ah;
                u32 (*bf)[4] = (p == 2) ? bl : bh;
#pragma unroll
                for (int mi = 0; mi < 2; mi++)
#pragma unroll
                    for (int ni = 0; ni < 4; ni++) {
                        mma16816(acc[mi][2 * ni + 0], af[mi], bf[ni][0], bf[ni][p0]);
                        mma16816(acc[mi][2 * ni + 1], af[mi], bf[ni][q0], bf[ni][3]);
                    }
            }
        }
        __syncthreads();
    }

    // epilogue
    const int mwarp = m0 + wm * 32;
    const int nwarp = n0 + wn * 64;
#pragma unroll
    for (int mi = 0; mi < 2; mi++) {
        const int r0 = mwarp + mi * 16 + (lane >> 2);
        float br0 = 0.f, br1 = 0.f;
        if (BIASROW) { br0 = bias[z * biasZ + r0]; br1 = bias[z * biasZ + r0 + 8]; }
#pragma unroll
        for (int nj = 0; nj < 8; nj++) {
            const int col = nwarp + nj * 8 + (lane & 3) * 2;
            const float* d = acc[mi][nj];
            float v00 = d[0] * scale + br0;
            float v01 = d[1] * scale + br0;
            float v10 = d[2] * scale + br1;
            float v11 = d[3] * scale + br1;
            const size_t i0 = (size_t)z * sC + (size_t)r0 * ldc + col;
            const size_t i1 = i0 + (size_t)8 * ldc;
            if (SPLIT) {
                u32 h, l;
                split2h(v00, v01, h, l);
                *(u32*)(Ch + i0) = h; *(u32*)(Cl + i0) = l;
                split2h(v10, v11, h, l);
                *(u32*)(Ch + i1) = h; *(u32*)(Cl + i1) = l;
            } else {
                *(float2*)(C + i0) = make_float2(v00, v01);
                *(float2*)(C + i1) = make_float2(v10, v11);
            }
        }
    }
}

// ---------------- elementwise kernels ----------------
__global__ void xsplit_sum(const float* __restrict__ x, half* __restrict__ xh,
                           half* __restrict__ xl, float* __restrict__ sx)
{
    const int r = blockIdx.x, tid = threadIdx.x;
    const float4* in = (const float4*)(x + (size_t)r * TT);
    uint2* oh = (uint2*)(xh + (size_t)r * TT);
    uint2* ol = (uint2*)(xl + (size_t)r * TT);
    float sum = 0.f;
#pragma unroll
    for (int i = 0; i < 4; i++) {
        const int idx = tid + i * 256;
        float4 v = in[idx];
        sum += v.x + v.y + v.z + v.w;
        uint2 h, l;
        split2h(v.x, v.y, h.x, l.x);
        split2h(v.z, v.w, h.y, l.y);
        oh[idx] = h;
        ol[idx] = l;
    }
#pragma unroll
    for (int o = 16; o > 0; o >>= 1) sum += __shfl_xor_sync(~0u, sum, o);
    __shared__ float red[8];
    if ((tid & 31) == 0) red[tid >> 5] = sum;
    __syncthreads();
    if (tid == 0) {
        float t = 0.f;
#pragma unroll
        for (int i = 0; i < 8; i++) t += red[i];
        sx[r] = t;
    }
}

__global__ void esplit3(const float* __restrict__ w0, const float* __restrict__ w1,
                        const float* __restrict__ w2, half* __restrict__ oh0,
                        half* __restrict__ ol0, half* __restrict__ oh1,
                        half* __restrict__ ol1, half* __restrict__ oh2,
                        half* __restrict__ ol2)
{
    const int which = blockIdx.y;
    const float* in = which == 0 ? w0 : (which == 1 ? w1 : w2);
    half* oh = which == 0 ? oh0 : (which == 1 ? oh1 : oh2);
    half* ol = which == 0 ? ol0 : (which == 1 ? ol1 : ol2);
    size_t i = ((size_t)blockIdx.x * blockDim.x + threadIdx.x) * 4;
    float4 v = *(const float4*)(in + i);
    uint2 h, l;
    split2h(v.x, v.y, h.x, l.x);
    split2h(v.z, v.w, h.y, l.y);
    *(uint2*)(oh + i) = h;
    *(uint2*)(ol + i) = l;
}

__global__ void gcombine_sym(const float* __restrict__ part, half* __restrict__ gh,
                             half* __restrict__ gl)
{
    __shared__ float t[32][33];
    const int ti = c_ti[blockIdx.y], tj = c_tj[blockIdx.y];
    const int sxo = (blockIdx.x & 3) * 32, syo = (blockIdx.x >> 2) * 32;
    const int b = blockIdx.z;
    const int r0 = ti * 128 + syo, c0 = tj * 128 + sxo;
    const int tx = threadIdx.x, ty = threadIdx.y;
    const float* pz = part + (size_t)b * KSPL_G * CCSQ;
    half* ghb = gh + (size_t)b * CCSQ;
    half* glb = gl + (size_t)b * CCSQ;
#pragma unroll
    for (int p = 0; p < 4; p++) {
        const int r = r0 + ty + p * 8;
        const size_t w = (size_t)r * CC + c0 + tx;
        float s = pz[w] + pz[w + CCSQ] + pz[w + 2 * CCSQ] + pz[w + 3 * CCSQ];
        t[ty + p * 8][tx] = s;
        __half h = __float2half_rn(s);
        ghb[w] = h;
        glb[w] = __float2half_rn(s - __half2float(h));
    }
    if (ti != tj) {
        __syncthreads();
#pragma unroll
        for (int p = 0; p < 4; p++) {
            float s = t[tx][ty + p * 8];
            const size_t w = (size_t)(c0 + ty + p * 8) * CC + r0 + tx;
            __half h = __float2half_rn(s);
            ghb[w] = h;
            glb[w] = __float2half_rn(s - __half2float(h));
        }
    }
}

__global__ void matvec_w(const float* __restrict__ Wq, const float* __restrict__ Wk,
                         const float* __restrict__ sx, float* __restrict__ w1,
                         float* __restrict__ w2)
{
    const int w = threadIdx.x >> 5, lane = threadIdx.x & 31;
    const int c = blockIdx.x * 8 + w, b = blockIdx.z;
    const float* W = blockIdx.y ? Wk : Wq;
    float* outp = blockIdx.y ? w2 : w1;
    const float4* Wr = (const float4*)(W + (size_t)c * CC);
    const float4* sv = (const float4*)(sx + b * CC);
    float s = 0.f;
#pragma unroll
    for (int i = 0; i < 4; i++) {
        float4 a = Wr[lane + 32 * i], xv = sv[lane + 32 * i];
        s += a.x * xv.x + a.y * xv.y + a.z * xv.z + a.w * xv.w;
    }
#pragma unroll
    for (int o = 16; o > 0; o >>= 1) s += __shfl_xor_sync(~0u, s, o);
    if (lane == 0) outp[b * CC + c] = s;
}

__global__ void softmax_corr(const float* __restrict__ d, const float* __restrict__ w1,
                             const float* __restrict__ w2, const float* __restrict__ bq,
                             const float* __restrict__ bk, const float* __restrict__ bv,
                             half* __restrict__ ah, half* __restrict__ al,
                             float* __restrict__ pb)
{
    const int gw = (blockIdx.x * blockDim.x + threadIdx.x) >> 5;
    const int lane = threadIdx.x & 31;
    const int b = gw >> 9, c = gw & 511;
    const float bqc = bq[c], w1c = w1[b * CC + c];
    const float4* r = (const float4*)(d + (size_t)gw * CC);
    const float4* w2r = (const float4*)(w2 + b * CC);
    const float4* bkr = (const float4*)bk;
    const float4* bvr = (const float4*)bv;

    float4 v[4], bvv[4];
    float mx = -1e30f;
#pragma unroll
    for (int i = 0; i < 4; i++) {
        const int idx = lane + 32 * i;
        float4 dv = r[idx], w2v = w2r[idx], bkv = bkr[idx];
        bvv[i] = bvr[idx];
        v[i].x = dv.x + SCALE_F * (bqc * (w2v.x + (float)TT * bkv.x) + w1c * bkv.x);
        v[i].y = dv.y + SCALE_F * (bqc * (w2v.y + (float)TT * bkv.y) + w1c * bkv.y);
        v[i].z = dv.z + SCALE_F * (bqc * (w2v.z + (float)TT * bkv.z) + w1c * bkv.z);
        v[i].w = dv.w + SCALE_F * (bqc * (w2v.w + (float)TT * bkv.w) + w1c * bkv.w);
        mx = fmaxf(mx, fmaxf(fmaxf(v[i].x, v[i].y), fmaxf(v[i].z, v[i].w)));
    }
#pragma unroll
    for (int o = 16; o > 0; o >>= 1) mx = fmaxf(mx, __shfl_xor_sync(~0u, mx, o));
    float s = 0.f;
#pragma unroll
    for (int i = 0; i < 4; i++) {
        v[i].x = expf(v[i].x - mx); v[i].y = expf(v[i].y - mx);
        v[i].z = expf(v[i].z - mx); v[i].w = expf(v[i].w - mx);
        s += v[i].x + v[i].y + v[i].z + v[i].w;
    }
#pragma unroll
    for (int o = 16; o > 0; o >>= 1) s += __shfl_xor_sync(~0u, s, o);
    const float inv = 1.0f / s;
    float dotbv = 0.f;
#pragma unroll
    for (int i = 0; i < 4; i++) {
        v[i].x *= inv; v[i].y *= inv; v[i].z *= inv; v[i].w *= inv;
        dotbv += v[i].x * bvv[i].x + v[i].y * bvv[i].y + v[i].z * bvv[i].z + v[i].w * bvv[i].w;
        uint2 h, l;
        split2h(v[i].x, v[i].y, h.x, l.x);
        split2h(v[i].z, v[i].w, h.y, l.y);
        size_t o = (size_t)gw * CC + 4 * (lane + 32 * i);
        *(uint2*)(ah + o) = h;
        *(uint2*)(al + o) = l;
    }
#pragma unroll
    for (int o = 16; o > 0; o >>= 1) dotbv += __shfl_xor_sync(~0u, dotbv, o);
    if (lane == 0) pb[gw] = dotbv;
}

// ---------------- launch ----------------
extern "C" void kernel_launch(void* const* d_in, const int* in_sizes, int n_in,
                              void* d_out, int out_size)
{
    (void)in_sizes; (void)n_in; (void)out_size;
    const float* x  = (const float*)d_in[0];
    const float* Wq = (const float*)d_in[1];
    const float* bq = (const float*)d_in[2];
    const float* Wk = (const float*)d_in[3];
    const float* bk = (const float*)d_in[4];
    const float* Wv = (const float*)d_in[5];
    const float* bv = (const float*)d_in[6];
    float* out = (float*)d_out;

    half *xh, *xl, *wqh, *wql, *wkh, *wkl, *wvh, *wvl;
    half *Gh, *Gl, *t2h, *t2l, *aH, *aL, *Ph, *Pl;
    float *part, *dots, *sx, *w1, *w2, *pb;
    cudaGetSymbolAddress((void**)&xh, g_x_h);
    cudaGetSymbolAddress((void**)&xl, g_x_l);
    cudaGetSymbolAddress((void**)&wqh, g_wq_h);
    cudaGetSymbolAddress((void**)&wql, g_wq_l);
    cudaGetSymbolAddress((void**)&wkh, g_wk_h);
    cudaGetSymbolAddress((void**)&wkl, g_wk_l);
    cudaGetSymbolAddress((void**)&wvh, g_wv_h);
    cudaGetSymbolAddress((void**)&wvl, g_wv_l);
    cudaGetSymbolAddress((void**)&part, g_part);
    cudaGetSymbolAddress((void**)&Gh, g_G_h);
    cudaGetSymbolAddress((void**)&Gl, g_G_l);
    cudaGetSymbolAddress((void**)&t2h, g_t2_h);
    cudaGetSymbolAddress((void**)&t2l, g_t2_l);
    cudaGetSymbolAddress((void**)&dots, g_dots);
    cudaGetSymbolAddress((void**)&aH, g_a_h);
    cudaGetSymbolAddress((void**)&aL, g_a_l);
    cudaGetSymbolAddress((void**)&Ph, g_P_h);
    cudaGetSymbolAddress((void**)&Pl, g_P_l);
    cudaGetSymbolAddress((void**)&sx, g_sx);
    cudaGetSymbolAddress((void**)&w1, g_w1);
    cudaGetSymbolAddress((void**)&w2, g_w2);
    cudaGetSymbolAddress((void**)&pb, g_pb);

    const size_t CT = (size_t)CC * TT;
    // dyn smem: 2 stages + 1KB align pad
    const int SM_G   = 2 * (2 * 256 * 128 + 32768) + 1024;  // BM=256, NPROD=3 -> 197632
    const int SM_128_3 = 2 * (2 * 128 * 128 + 32768) + 1024; // 132096
    const int SM_128_2 = 2 * (2 * 128 * 128 + 16384) + 1024; // 99328
    const int SM_OUT = 2 * (2 * 256 * 128 + 16384) + 1024;  // BM=256, NPROD=2 -> 164864

    cudaFuncSetAttribute(gemm_mma<256, false, false, KSPL_G, true, false, 3>, cudaFuncAttributeMaxDynamicSharedMemorySize, SM_G);
    cudaFuncSetAttribute(gemm_mma<128, false, true, 1, false, false, 3>, cudaFuncAttributeMaxDynamicSharedMemorySize, SM_128_3);
    cudaFuncSetAttribute(gemm_mma<128, false, false, 1, false, false, 3>, cudaFuncAttributeMaxDynamicSharedMemorySize, SM_128_3);
    cudaFuncSetAttribute(gemm_mma<128, false, true, 1, false, true, 2>, cudaFuncAttributeMaxDynamicSharedMemorySize, SM_128_2);
    cudaFuncSetAttribute(gemm_mma<256, true, false, 1, false, true, 2>, cudaFuncAttributeMaxDynamicSharedMemorySize, SM_OUT);

    // prep
    xsplit_sum<<<BB * CC, 256>>>(x, xh, xl, sx);
    esplit3<<<dim3(CCSQ / 1024, 3), 256>>>(Wq, Wk, Wv, wqh, wql, wkh, wkl, wvh, wvl);
    matvec_w<<<dim3(CC / 8, 2, BB), 256>>>(Wq, Wk, sx, w1, w2);

    // G = x x^T : 256x128 triangular blocks, split-K x4 partials (3-product)
    gemm_mma<256, false, false, KSPL_G, true, false, 3><<<dim3(6, 1, BB * KSPL_G), 512, SM_G>>>(
        xh, xl, CT, TT, xh, xl, CT, TT, part, nullptr, nullptr,
        CCSQ, CC, nullptr, 0, 1.0f, TT / KSPL_G);
    gcombine_sym<<<dim3(16, 10, BB), dim3(32, 8)>>>(part, Gh, Gl);

    // t2 = Wq * G (3-product; precision critical)
    gemm_mma<128, false, true, 1, false, false, 3><<<dim3(4, 4, BB), 256, SM_128_3>>>(
        wqh, wql, 0, CC, Gh, Gl, CCSQ, CC, nullptr, t2h, t2l,
        CCSQ, CC, nullptr, 0, 1.0f, CC);
    // dots = SCALE * t2 * Wk^T (3-product)
    gemm_mma<128, false, false, 1, false, false, 3><<<dim3(4, 4, BB), 256, SM_128_3>>>(
        t2h, t2l, CCSQ, CC, wkh, wkl, 0, CC, dots, nullptr, nullptr,
        CCSQ, CC, nullptr, 0, SCALE_F, CC);
    // softmax + corrections + pb + attn split
    softmax_corr<<<BB * CC / 4, 128>>>(dots, w1, w2, bq, bk, bv, aH, aL, pb);
    // P = attn * Wv  (2-product)
    gemm_mma<128, false, true, 1, false, true, 2><<<dim3(4, 4, BB), 256, SM_128_2>>>(
        aH, aL, CCSQ, CC, wvh, wvh, 0, CC, nullptr, Ph, Pl,
        CCSQ, CC, nullptr, 0, 1.0f, CC);
    // out = P * x + pb  (2-product, BM=256)
    gemm_mma<256, true, false, 1, false, true, 2><<<dim3(TT / 128, CC / 256, BB), 512, SM_OUT>>>(
        Ph, Pl, CCSQ, CC, xh, xh, CT, TT, out, nullptr, nullptr,
        CT, TT, pb, CC, 1.0f, CC);
}

// round 12
// speedup vs baseline: 1.3101x; 1.3101x over previous
#include <cuda_runtime.h>
#include <cuda_fp16.h>

typedef unsigned int u32;

#define BB 8
#define CC 512
#define TT 4096
#define SCALE_F 0.125f
#define NELEM ((size_t)BB * CC * TT)
#define CCSQ ((size_t)CC * CC)
#define KSPL_G 4

// ---------------- scratch ----------------
__device__ half g_x_h[NELEM];
__device__ half g_x_l[NELEM];
__device__ half g_wq_h[CCSQ];
__device__ half g_wq_l[CCSQ];
__device__ half g_wk_h[CCSQ];
__device__ half g_wk_l[CCSQ];
__device__ half g_wv_h[CCSQ];
__device__ half g_wv_l[CCSQ];
__device__ float g_part[(size_t)KSPL_G * BB * CCSQ];
__device__ half g_G_h[(size_t)BB * CCSQ];
__device__ half g_G_l[(size_t)BB * CCSQ];
__device__ half g_t2_h[(size_t)BB * CCSQ];
__device__ half g_t2_l[(size_t)BB * CCSQ];
__device__ float g_dots[(size_t)BB * CCSQ];
__device__ half g_a_h[(size_t)BB * CCSQ];
__device__ half g_P_h[(size_t)BB * CCSQ];
__device__ half g_P_l[(size_t)BB * CCSQ];
__device__ float g_sx[BB * CC];
__device__ float g_w1[BB * CC];
__device__ float g_w2[BB * CC];
__device__ float g_pb[BB * CC];

// upper-triangle 128-tile map for G (4x4 tiles -> 10)
__device__ __constant__ int c_ti[10] = {0, 0, 0, 0, 1, 1, 1, 2, 2, 3};
__device__ __constant__ int c_tj[10] = {0, 1, 2, 3, 1, 2, 3, 2, 3, 3};

// ---------------- helpers ----------------
__device__ __forceinline__ u32 smem_u32(const void* p) {
    u32 a;
    asm("{ .reg .u64 t; cvta.to.shared.u64 t, %1; cvt.u32.u64 %0, t; }" : "=r"(a) : "l"(p));
    return a;
}
__device__ __forceinline__ void split2h(float a, float b, u32& h, u32& l) {
    __half h0 = __float2half_rn(a), h1 = __float2half_rn(b);
    __half l0 = __float2half_rn(a - __half2float(h0));
    __half l1 = __float2half_rn(b - __half2float(h1));
    __half2 hh = __halves2half2(h0, h1), ll = __halves2half2(l0, l1);
    h = *(u32*)&hh;
    l = *(u32*)&ll;
}
__device__ __forceinline__ void pack2h(float a, float b, u32& h) {
    __half2 hh = __halves2half2(__float2half_rn(a), __float2half_rn(b));
    h = *(u32*)&hh;
}
__device__ __forceinline__ void ldsm4(u32& r0, u32& r1, u32& r2, u32& r3, u32 addr) {
    asm volatile("ldmatrix.sync.aligned.m8n8.x4.shared.b16 {%0,%1,%2,%3}, [%4];"
                 : "=r"(r0), "=r"(r1), "=r"(r2), "=r"(r3) : "r"(addr));
}
__device__ __forceinline__ void ldsm4t(u32& r0, u32& r1, u32& r2, u32& r3, u32 addr) {
    asm volatile("ldmatrix.sync.aligned.m8n8.x4.trans.shared.b16 {%0,%1,%2,%3}, [%4];"
                 : "=r"(r0), "=r"(r1), "=r"(r2), "=r"(r3) : "r"(addr));
}
__device__ __forceinline__ void mma16816(float* d, const u32* a, u32 b0, u32 b1) {
    asm volatile(
        "mma.sync.aligned.m16n8k16.row.col.f32.f16.f16.f32 "
        "{%0,%1,%2,%3}, {%4,%5,%6,%7}, {%8,%9}, {%0,%1,%2,%3};"
        : "+f"(d[0]), "+f"(d[1]), "+f"(d[2]), "+f"(d[3])
        : "r"(a[0]), "r"(a[1]), "r"(a[2]), "r"(a[3]), "r"(b0), "r"(b1));
}
// cp.async 128 rows x 64 half (128B rows), SW swizzle; 256 threads.
__device__ __forceinline__ void cp_tile(u32 sdst, const half* g, int ld, int tid) {
    const int seg = tid & 7;
    const int r0 = tid >> 3;
    const char* gc = (const char*)g + seg * 16;
#pragma unroll
    for (int p = 0; p < 4; p++) {
        int row = p * 32 + r0;
        u32 dst = sdst + row * 128 + ((seg ^ (row & 7)) << 4);
        const void* src = gc + (size_t)row * ld * sizeof(half);
        asm volatile("cp.async.cg.shared.global [%0], [%1], 16;" :: "r"(dst), "l"(src) : "memory");
    }
}
// cp.async 64 rows x 128 half (256B rows); 256 threads.
__device__ __forceinline__ void cp_tileB(u32 sdst, const half* g, int ld, int tid) {
    const int seg = tid & 15;
    const int r0 = tid >> 4;
    const char* gc = (const char*)g + seg * 16;
#pragma unroll
    for (int p = 0; p < 4; p++) {
        int row = p * 16 + r0;
        u32 dst = sdst + row * 256 + ((seg ^ (row & 7)) << 4);
        const void* src = gc + (size_t)row * ld * sizeof(half);
        asm volatile("cp.async.cg.shared.global [%0], [%1], 16;" :: "r"(dst), "l"(src) : "memory");
    }
}

// ---------------------------------------------------------------------------
// GEMM D[m,n] = scale*(A.B) + bias; fp16 2-term split.
// NPROD=3: AhBh+AlBh+AhBl.  NPROD=2: AhBh+AlBh.  NPROD=1: AhBh only
// (Al/Bl never loaded; stage = 32KB).
// BM=128, BN=128, BK=64. 8 warps (4M x 2N). 2-stage cp.async.
// BTRANS: B is [k][n] n-contig via ldmatrix.trans. TRI: triangular G grid.
// ---------------------------------------------------------------------------
template <bool BIASROW, bool SPLIT, int KSPL, bool TRI, bool BTRANS, int NPROD>
__global__ __launch_bounds__(256) void gemm_mma(
    const half* __restrict__ Ah, const half* __restrict__ Al, size_t sA, int lda,
    const half* __restrict__ Bh, const half* __restrict__ Bl, size_t sB, int ldb,
    float* __restrict__ C, half* __restrict__ Ch, half* __restrict__ Cl,
    size_t sC, int ldc, const float* __restrict__ bias, int biasZ,
    float scale, int K)
{
    constexpr u32 NA = (NPROD >= 2) ? 2 : 1;                 // A tiles per stage
    constexpr u32 NB = (NPROD == 3) ? 2 : 1;                 // B tiles per stage
    constexpr u32 STAGE = NA * 16384 + NB * 16384;

    extern __shared__ char dyn[];
    char* dg = (char*)(((size_t)dyn + 1023) & ~(size_t)1023);
    const u32 base = smem_u32(dg);

    const int tid = threadIdx.x, wid = tid >> 5, lane = tid & 31;
    const int z = blockIdx.z;
    const int batch = z / KSPL, ksl = z - batch * KSPL;
    const int m0 = TRI ? c_ti[blockIdx.x] * 128 : blockIdx.y * 128;
    const int n0 = TRI ? c_tj[blockIdx.x] * 128 : blockIdx.x * 128;
    const int wm = wid & 3, wn = wid >> 2;

    const half* pAh = Ah + (size_t)batch * sA + (size_t)ksl * K + (size_t)m0 * lda;
    const half* pAl = Al + (size_t)batch * sA + (size_t)ksl * K + (size_t)m0 * lda;
    const half* pBh;
    const half* pBl;
    if (BTRANS) {
        pBh = Bh + (size_t)batch * sB + (size_t)(ksl * K) * ldb + n0;
        pBl = Bl + (size_t)batch * sB + (size_t)(ksl * K) * ldb + n0;
    } else {
        pBh = Bh + (size_t)batch * sB + (size_t)ksl * K + (size_t)n0 * ldb;
        pBl = Bl + (size_t)batch * sB + (size_t)ksl * K + (size_t)n0 * ldb;
    }

    const int NCH = K >> 6;

    float acc[2][8][4];
#pragma unroll
    for (int i = 0; i < 2; i++)
#pragma unroll
        for (int j = 0; j < 8; j++)
#pragma unroll
            for (int t = 0; t < 4; t++) acc[i][j][t] = 0.0f;

    // prologue
    cp_tile(base, pAh, lda, tid);
    if (NPROD >= 2) cp_tile(base + 16384, pAl, lda, tid);
    const u32 bofs = NA * 16384;
    if (BTRANS) {
        cp_tileB(base + bofs, pBh, ldb, tid);
        if (NPROD == 3) cp_tileB(base + bofs + 16384, pBl, ldb, tid);
    } else {
        cp_tile(base + bofs, pBh, ldb, tid);
        if (NPROD == 3) cp_tile(base + bofs + 16384, pBl, ldb, tid);
    }
    asm volatile("cp.async.commit_group;" ::: "memory");

    for (int c = 0; c < NCH; c++) {
        const int st = c & 1;
        if (c + 1 < NCH) {
            const u32 sb = base + (st ^ 1) * STAGE;
            const int ko = (c + 1) * 64;
            cp_tile(sb, pAh + ko, lda, tid);
            if (NPROD >= 2) cp_tile(sb + 16384, pAl + ko, lda, tid);
            if (BTRANS) {
                cp_tileB(sb + bofs, pBh + (size_t)ko * ldb, ldb, tid);
                if (NPROD == 3) cp_tileB(sb + bofs + 16384, pBl + (size_t)ko * ldb, ldb, tid);
            } else {
                cp_tile(sb + bofs, pBh + ko, ldb, tid);
                if (NPROD == 3) cp_tile(sb + bofs + 16384, pBl + ko, ldb, tid);
            }
        }
        asm volatile("cp.async.commit_group;" ::: "memory");
        asm volatile("cp.async.wait_group 1;" ::: "memory");
        __syncthreads();

        const u32 sAh = base + st * STAGE;
        const u32 sAl = sAh + 16384;
        const u32 sBh = sAh + bofs, sBl = sAh + bofs + 16384;

#pragma unroll
        for (int ks = 0; ks < 4; ks++) {
            u32 ah[2][4], al[2][4];
#pragma unroll
            for (int mi = 0; mi < 2; mi++) {
                const int row = wm * 32 + mi * 16 + (lane & 15);
                const u32 off = row * 128 + ((((ks << 1) | (lane >> 4)) ^ (row & 7)) << 4);
                ldsm4(ah[mi][0], ah[mi][1], ah[mi][2], ah[mi][3], sAh + off);
                if (NPROD >= 2)
                    ldsm4(al[mi][0], al[mi][1], al[mi][2], al[mi][3], sAl + off);
            }
            u32 bh[4][4], bl[4][4];
#pragma unroll
            for (int ni = 0; ni < 4; ni++) {
                if (BTRANS) {
                    const int row = ks * 16 + (lane & 15);
                    const int chunk = wn * 8 + ni * 2 + (lane >> 4);
                    const u32 off = row * 256 + ((chunk ^ (row & 7)) << 4);
                    ldsm4t(bh[ni][0], bh[ni][1], bh[ni][2], bh[ni][3], sBh + off);
                    if (NPROD == 3) ldsm4t(bl[ni][0], bl[ni][1], bl[ni][2], bl[ni][3], sBl + off);
                } else {
                    const int row = wn * 64 + ni * 16 + (lane & 15);
                    const u32 off = row * 128 + ((((ks << 1) | (lane >> 4)) ^ (row & 7)) << 4);
                    ldsm4(bh[ni][0], bh[ni][1], bh[ni][2], bh[ni][3], sBh + off);
                    if (NPROD == 3) ldsm4(bl[ni][0], bl[ni][1], bl[ni][2], bl[ni][3], sBl + off);
                }
            }
            const int p0 = BTRANS ? 1 : 2;   // k-hi fragment index
            const int q0 = BTRANS ? 2 : 1;   // n+8 fragment base
#pragma unroll
            for (int p = 0; p < NPROD; p++) {
                u32 (*af)[4] = (p == 1) ? al : ah;
                u32 (*bf)[4] = (p == 2) ? bl : bh;
#pragma unroll
                for (int mi = 0; mi < 2; mi++)
#pragma unroll
                    for (int ni = 0; ni < 4; ni++) {
                        mma16816(acc[mi][2 * ni + 0], af[mi], bf[ni][0], bf[ni][p0]);
                        mma16816(acc[mi][2 * ni + 1], af[mi], bf[ni][q0], bf[ni][3]);
                    }
            }
        }
        __syncthreads();
    }

    // epilogue
    const int mwarp = m0 + wm * 32;
    const int nwarp = n0 + wn * 64;
#pragma unroll
    for (int mi = 0; mi < 2; mi++) {
        const int r0 = mwarp + mi * 16 + (lane >> 2);
        float br0 = 0.f, br1 = 0.f;
        if (BIASROW) { br0 = bias[z * biasZ + r0]; br1 = bias[z * biasZ + r0 + 8]; }
#pragma unroll
        for (int nj = 0; nj < 8; nj++) {
            const int col = nwarp + nj * 8 + (lane & 3) * 2;
            const float* d = acc[mi][nj];
            float v00 = d[0] * scale + br0;
            float v01 = d[1] * scale + br0;
            float v10 = d[2] * scale + br1;
            float v11 = d[3] * scale + br1;
            const size_t i0 = (size_t)z * sC + (size_t)r0 * ldc + col;
            const size_t i1 = i0 + (size_t)8 * ldc;
            if (SPLIT) {
                if (Cl) {
                    u32 h, l;
                    split2h(v00, v01, h, l);
                    *(u32*)(Ch + i0) = h; *(u32*)(Cl + i0) = l;
                    split2h(v10, v11, h, l);
                    *(u32*)(Ch + i1) = h; *(u32*)(Cl + i1) = l;
                } else {
                    u32 h;
                    pack2h(v00, v01, h); *(u32*)(Ch + i0) = h;
                    pack2h(v10, v11, h); *(u32*)(Ch + i1) = h;
                }
            } else {
                *(float2*)(C + i0) = make_float2(v00, v01);
                *(float2*)(C + i1) = make_float2(v10, v11);
            }
        }
    }
}

// ---------------- elementwise kernels ----------------
__global__ void xsplit_sum(const float* __restrict__ x, half* __restrict__ xh,
                           half* __restrict__ xl, float* __restrict__ sx)
{
    const int r = blockIdx.x, tid = threadIdx.x;
    const float4* in = (const float4*)(x + (size_t)r * TT);
    uint2* oh = (uint2*)(xh + (size_t)r * TT);
    uint2* ol = (uint2*)(xl + (size_t)r * TT);
    float sum = 0.f;
#pragma unroll
    for (int i = 0; i < 4; i++) {
        const int idx = tid + i * 256;
        float4 v = in[idx];
        sum += v.x + v.y + v.z + v.w;
        uint2 h, l;
        split2h(v.x, v.y, h.x, l.x);
        split2h(v.z, v.w, h.y, l.y);
        oh[idx] = h;
        ol[idx] = l;
    }
#pragma unroll
    for (int o = 16; o > 0; o >>= 1) sum += __shfl_xor_sync(~0u, sum, o);
    __shared__ float red[8];
    if ((tid & 31) == 0) red[tid >> 5] = sum;
    __syncthreads();
    if (tid == 0) {
        float t = 0.f;
#pragma unroll
        for (int i = 0; i < 8; i++) t += red[i];
        sx[r] = t;
    }
}

__global__ void esplit3(const float* __restrict__ w0, const float* __restrict__ w1,
                        const float* __restrict__ w2, half* __restrict__ oh0,
                        half* __restrict__ ol0, half* __restrict__ oh1,
                        half* __restrict__ ol1, half* __restrict__ oh2,
                        half* __restrict__ ol2)
{
    const int which = blockIdx.y;
    const float* in = which == 0 ? w0 : (which == 1 ? w1 : w2);
    half* oh = which == 0 ? oh0 : (which == 1 ? oh1 : oh2);
    half* ol = which == 0 ? ol0 : (which == 1 ? ol1 : ol2);
    size_t i = ((size_t)blockIdx.x * blockDim.x + threadIdx.x) * 4;
    float4 v = *(const float4*)(in + i);
    uint2 h, l;
    split2h(v.x, v.y, h.x, l.x);
    split2h(v.z, v.w, h.y, l.y);
    *(uint2*)(oh + i) = h;
    *(uint2*)(ol + i) = l;
}

__global__ void gcombine_sym(const float* __restrict__ part, half* __restrict__ gh,
                             half* __restrict__ gl)
{
    __shared__ float t[32][33];
    const int ti = c_ti[blockIdx.y], tj = c_tj[blockIdx.y];
    const int sxo = (blockIdx.x & 3) * 32, syo = (blockIdx.x >> 2) * 32;
    const int b = blockIdx.z;
    const int r0 = ti * 128 + syo, c0 = tj * 128 + sxo;
    const int tx = threadIdx.x, ty = threadIdx.y;
    const float* pz = part + (size_t)b * KSPL_G * CCSQ;
    half* ghb = gh + (size_t)b * CCSQ;
    half* glb = gl + (size_t)b * CCSQ;
#pragma unroll
    for (int p = 0; p < 4; p++) {
        const int r = r0 + ty + p * 8;
        const size_t w = (size_t)r * CC + c0 + tx;
        float s = pz[w] + pz[w + CCSQ] + pz[w + 2 * CCSQ] + pz[w + 3 * CCSQ];
        t[ty + p * 8][tx] = s;
        __half h = __float2half_rn(s);
        ghb[w] = h;
        glb[w] = __float2half_rn(s - __half2float(h));
    }
    if (ti != tj) {
        __syncthreads();
#pragma unroll
        for (int p = 0; p < 4; p++) {
            float s = t[tx][ty + p * 8];
            const size_t w = (size_t)(c0 + ty + p * 8) * CC + r0 + tx;
            __half h = __float2half_rn(s);
            ghb[w] = h;
            glb[w] = __float2half_rn(s - __half2float(h));
        }
    }
}

__global__ void matvec_w(const float* __restrict__ Wq, const float* __restrict__ Wk,
                         const float* __restrict__ sx, float* __restrict__ w1,
                         float* __restrict__ w2)
{
    const int w = threadIdx.x >> 5, lane = threadIdx.x & 31;
    const int c = blockIdx.x * 8 + w, b = blockIdx.z;
    const float* W = blockIdx.y ? Wk : Wq;
    float* outp = blockIdx.y ? w2 : w1;
    const float4* Wr = (const float4*)(W + (size_t)c * CC);
    const float4* sv = (const float4*)(sx + b * CC);
    float s = 0.f;
#pragma unroll
    for (int i = 0; i < 4; i++) {
        float4 a = Wr[lane + 32 * i], xv = sv[lane + 32 * i];
        s += a.x * xv.x + a.y * xv.y + a.z * xv.z + a.w * xv.w;
    }
#pragma unroll
    for (int o = 16; o > 0; o >>= 1) s += __shfl_xor_sync(~0u, s, o);
    if (lane == 0) outp[b * CC + c] = s;
}

// softmax + rank-1 corrections + pb = attn*bv; writes attn hi only
__global__ void softmax_corr(const float* __restrict__ d, const float* __restrict__ w1,
                             const float* __restrict__ w2, const float* __restrict__ bq,
                             const float* __restrict__ bk, const float* __restrict__ bv,
                             half* __restrict__ ah, float* __restrict__ pb)
{
    const int gw = (blockIdx.x * blockDim.x + threadIdx.x) >> 5;
    const int lane = threadIdx.x & 31;
    const int b = gw >> 9, c = gw & 511;
    const float bqc = bq[c], w1c = w1[b * CC + c];
    const float4* r = (const float4*)(d + (size_t)gw * CC);
    const float4* w2r = (const float4*)(w2 + b * CC);
    const float4* bkr = (const float4*)bk;
    const float4* bvr = (const float4*)bv;

    float4 v[4], bvv[4];
    float mx = -1e30f;
#pragma unroll
    for (int i = 0; i < 4; i++) {
        const int idx = lane + 32 * i;
        float4 dv = r[idx], w2v = w2r[idx], bkv = bkr[idx];
        bvv[i] = bvr[idx];
        v[i].x = dv.x + SCALE_F * (bqc * (w2v.x + (float)TT * bkv.x) + w1c * bkv.x);
        v[i].y = dv.y + SCALE_F * (bqc * (w2v.y + (float)TT * bkv.y) + w1c * bkv.y);
        v[i].z = dv.z + SCALE_F * (bqc * (w2v.z + (float)TT * bkv.z) + w1c * bkv.z);
        v[i].w = dv.w + SCALE_F * (bqc * (w2v.w + (float)TT * bkv.w) + w1c * bkv.w);
        mx = fmaxf(mx, fmaxf(fmaxf(v[i].x, v[i].y), fmaxf(v[i].z, v[i].w)));
    }
#pragma unroll
    for (int o = 16; o > 0; o >>= 1) mx = fmaxf(mx, __shfl_xor_sync(~0u, mx, o));
    float s = 0.f;
#pragma unroll
    for (int i = 0; i < 4; i++) {
        v[i].x = expf(v[i].x - mx); v[i].y = expf(v[i].y - mx);
        v[i].z = expf(v[i].z - mx); v[i].w = expf(v[i].w - mx);
        s += v[i].x + v[i].y + v[i].z + v[i].w;
    }
#pragma unroll
    for (int o = 16; o > 0; o >>= 1) s += __shfl_xor_sync(~0u, s, o);
    const float inv = 1.0f / s;
    float dotbv = 0.f;
#pragma unroll
    for (int i = 0; i < 4; i++) {
        v[i].x *= inv; v[i].y *= inv; v[i].z *= inv; v[i].w *= inv;
        dotbv += v[i].x * bvv[i].x + v[i].y * bvv[i].y + v[i].z * bvv[i].z + v[i].w * bvv[i].w;
        uint2 h;
        pack2h(v[i].x, v[i].y, h.x);
        pack2h(v[i].z, v[i].w, h.y);
        size_t o = (size_t)gw * CC + 4 * (lane + 32 * i);
        *(uint2*)(ah + o) = h;
    }
#pragma unroll
    for (int o = 16; o > 0; o >>= 1) dotbv += __shfl_xor_sync(~0u, dotbv, o);
    if (lane == 0) pb[gw] = dotbv;
}

// ---------------- launch ----------------
extern "C" void kernel_launch(void* const* d_in, const int* in_sizes, int n_in,
                              void* d_out, int out_size)
{
    (void)in_sizes; (void)n_in; (void)out_size;
    const float* x  = (const float*)d_in[0];
    const float* Wq = (const float*)d_in[1];
    const float* bq = (const float*)d_in[2];
    const float* Wk = (const float*)d_in[3];
    const float* bk = (const float*)d_in[4];
    const float* Wv = (const float*)d_in[5];
    const float* bv = (const float*)d_in[6];
    float* out = (float*)d_out;

    half *xh, *xl, *wqh, *wql, *wkh, *wkl, *wvh, *wvl;
    half *Gh, *Gl, *t2h, *t2l, *aH, *Ph, *Pl;
    float *part, *dots, *sx, *w1, *w2, *pb;
    cudaGetSymbolAddress((void**)&xh, g_x_h);
    cudaGetSymbolAddress((void**)&xl, g_x_l);
    cudaGetSymbolAddress((void**)&wqh, g_wq_h);
    cudaGetSymbolAddress((void**)&wql, g_wq_l);
    cudaGetSymbolAddress((void**)&wkh, g_wk_h);
    cudaGetSymbolAddress((void**)&wkl, g_wk_l);
    cudaGetSymbolAddress((void**)&wvh, g_wv_h);
    cudaGetSymbolAddress((void**)&wvl, g_wv_l);
    cudaGetSymbolAddress((void**)&part, g_part);
    cudaGetSymbolAddress((void**)&Gh, g_G_h);
    cudaGetSymbolAddress((void**)&Gl, g_G_l);
    cudaGetSymbolAddress((void**)&t2h, g_t2_h);
    cudaGetSymbolAddress((void**)&t2l, g_t2_l);
    cudaGetSymbolAddress((void**)&dots, g_dots);
    cudaGetSymbolAddress((void**)&aH, g_a_h);
    cudaGetSymbolAddress((void**)&Ph, g_P_h);
    cudaGetSymbolAddress((void**)&Pl, g_P_l);
    cudaGetSymbolAddress((void**)&sx, g_sx);
    cudaGetSymbolAddress((void**)&w1, g_w1);
    cudaGetSymbolAddress((void**)&w2, g_w2);
    cudaGetSymbolAddress((void**)&pb, g_pb);

    const size_t CT = (size_t)CC * TT;
    const int SM_3 = 2 * (2 * 16384 + 2 * 16384) + 1024;  // NPROD=3: 132096
    const int SM_1 = 2 * (16384 + 16384) + 1024;          // NPROD=1: 66560

    cudaFuncSetAttribute(gemm_mma<false, false, KSPL_G, true, false, 3>, cudaFuncAttributeMaxDynamicSharedMemorySize, SM_3);
    cudaFuncSetAttribute(gemm_mma<false, true, 1, false, false, 3>, cudaFuncAttributeMaxDynamicSharedMemorySize, SM_3);
    cudaFuncSetAttribute(gemm_mma<false, false, 1, false, false, 3>, cudaFuncAttributeMaxDynamicSharedMemorySize, SM_3);
    cudaFuncSetAttribute(gemm_mma<false, true, 1, false, true, 1>, cudaFuncAttributeMaxDynamicSharedMemorySize, SM_1);
    cudaFuncSetAttribute(gemm_mma<true, false, 1, false, true, 1>, cudaFuncAttributeMaxDynamicSharedMemorySize, SM_1);

    // prep
    xsplit_sum<<<BB * CC, 256>>>(x, xh, xl, sx);
    esplit3<<<dim3(CCSQ / 1024, 3), 256>>>(Wq, Wk, Wv, wqh, wql, wkh, wkl, wvh, wvl);
    matvec_w<<<dim3(CC / 8, 2, BB), 256>>>(Wq, Wk, sx, w1, w2);

    // G = x x^T : upper-triangle 128-tiles, split-K x4 partials (3-product)
    gemm_mma<false, false, KSPL_G, true, false, 3><<<dim3(10, 1, BB * KSPL_G), 256, SM_3>>>(
        xh, xl, CT, TT, xh, xl, CT, TT, part, nullptr, nullptr,
        CCSQ, CC, nullptr, 0, 1.0f, TT / KSPL_G);
    gcombine_sym<<<dim3(16, 10, BB), dim3(32, 8)>>>(part, Gh, Gl);

    // t2 = Wq * G (3-product; precision critical)
    gemm_mma<false, true, 1, false, false, 3><<<dim3(4, 4, BB), 256, SM_3>>>(
        wqh, wql, 0, CC, Gh, Gl, CCSQ, CC, nullptr, t2h, t2l,
        CCSQ, CC, nullptr, 0, 1.0f, CC);
    // dots = SCALE * t2 * Wk^T (3-product)
    gemm_mma<false, false, 1, false, false, 3><<<dim3(4, 4, BB), 256, SM_3>>>(
        t2h, t2l, CCSQ, CC, wkh, wkl, 0, CC, dots, nullptr, nullptr,
        CCSQ, CC, nullptr, 0, SCALE_F, CC);
    // softmax + corrections + pb (attn hi only)
    softmax_corr<<<BB * CC / 4, 128>>>(dots, w1, w2, bq, bk, bv, aH, pb);
    // P = aH * Wv  (1-product; split output for out-GEMM A)
    gemm_mma<false, true, 1, false, true, 1><<<dim3(4, 4, BB), 256, SM_1>>>(
        aH, aH, CCSQ, CC, wvh, wvh, 0, CC, nullptr, Ph, Pl,
        CCSQ, CC, nullptr, 0, 1.0f, CC);
    // out = Ph * xh + pb  (1-product)
    gemm_mma<true, false, 1, false, true, 1><<<dim3(TT / 128, CC / 128, BB), 256, SM_1>>>(
        Ph, Ph, CCSQ, CC, xh, xh, CT, TT, out, nullptr, nullptr,
        CT, TT, pb, CC, 1.0f, CC);
}

// round 15
// speedup vs baseline: 1.3240x; 1.0106x over previous
#include <cuda_runtime.h>
#include <cuda_fp16.h>

typedef unsigned int u32;

#define BB 8
#define CC 512
#define TT 4096
#define SCALE_F 0.125f
#define NELEM ((size_t)BB * CC * TT)
#define CCSQ ((size_t)CC * CC)
#define KSPL_G 4

// ---------------- scratch ----------------
__device__ half g_x_h[NELEM];
__device__ half g_x_l[NELEM];
__device__ half g_wq_h[CCSQ];
__device__ half g_wq_l[CCSQ];
__device__ half g_wk_h[CCSQ];
__device__ half g_wk_l[CCSQ];
__device__ half g_wv_h[CCSQ];
__device__ half g_wv_l[CCSQ];
__device__ float g_part[(size_t)KSPL_G * BB * CCSQ];
__device__ half g_G_h[(size_t)BB * CCSQ];
__device__ half g_G_l[(size_t)BB * CCSQ];
__device__ half g_t2_h[(size_t)BB * CCSQ];
__device__ half g_t2_l[(size_t)BB * CCSQ];
__device__ float g_dots[(size_t)BB * CCSQ];
__device__ half g_a_h[(size_t)BB * CCSQ];
__device__ half g_P_h[(size_t)BB * CCSQ];
__device__ half g_P_l[(size_t)BB * CCSQ];
__device__ float g_sx[BB * CC];
__device__ float g_w1[BB * CC];
__device__ float g_w2[BB * CC];
__device__ float g_pb[BB * CC];

// upper-triangle 128-tile map for G (4x4 tiles -> 10)
__device__ __constant__ int c_ti[10] = {0, 0, 0, 0, 1, 1, 1, 2, 2, 3};
__device__ __constant__ int c_tj[10] = {0, 1, 2, 3, 1, 2, 3, 2, 3, 3};

// ---------------- helpers ----------------
__device__ __forceinline__ u32 smem_u32(const void* p) {
    u32 a;
    asm("{ .reg .u64 t; cvta.to.shared.u64 t, %1; cvt.u32.u64 %0, t; }" : "=r"(a) : "l"(p));
    return a;
}
__device__ __forceinline__ void split2h(float a, float b, u32& h, u32& l) {
    __half h0 = __float2half_rn(a), h1 = __float2half_rn(b);
    __half l0 = __float2half_rn(a - __half2float(h0));
    __half l1 = __float2half_rn(b - __half2float(h1));
    __half2 hh = __halves2half2(h0, h1), ll = __halves2half2(l0, l1);
    h = *(u32*)&hh;
    l = *(u32*)&ll;
}
__device__ __forceinline__ void pack2h(float a, float b, u32& h) {
    __half2 hh = __halves2half2(__float2half_rn(a), __float2half_rn(b));
    h = *(u32*)&hh;
}
__device__ __forceinline__ float2 unpack2h(u32 u) {
    __half2 h2 = *(__half2*)&u;
    return __half22float2(h2);
}
__device__ __forceinline__ void ldsm4(u32& r0, u32& r1, u32& r2, u32& r3, u32 addr) {
    asm volatile("ldmatrix.sync.aligned.m8n8.x4.shared.b16 {%0,%1,%2,%3}, [%4];"
                 : "=r"(r0), "=r"(r1), "=r"(r2), "=r"(r3) : "r"(addr));
}
__device__ __forceinline__ void ldsm4t(u32& r0, u32& r1, u32& r2, u32& r3, u32 addr) {
    asm volatile("ldmatrix.sync.aligned.m8n8.x4.trans.shared.b16 {%0,%1,%2,%3}, [%4];"
                 : "=r"(r0), "=r"(r1), "=r"(r2), "=r"(r3) : "r"(addr));
}
__device__ __forceinline__ void mma16816(float* d, const u32* a, u32 b0, u32 b1) {
    asm volatile(
        "mma.sync.aligned.m16n8k16.row.col.f32.f16.f16.f32 "
        "{%0,%1,%2,%3}, {%4,%5,%6,%7}, {%8,%9}, {%0,%1,%2,%3};"
        : "+f"(d[0]), "+f"(d[1]), "+f"(d[2]), "+f"(d[3])
        : "r"(a[0]), "r"(a[1]), "r"(a[2]), "r"(a[3]), "r"(b0), "r"(b1));
}
// fp16-accumulate variant (2x rate on legacy HMMA path); d = 2 u32 = 4 halves
__device__ __forceinline__ void mma16816h(u32* d, const u32* a, u32 b0, u32 b1) {
    asm volatile(
        "mma.sync.aligned.m16n8k16.row.col.f16.f16.f16.f16 "
        "{%0,%1}, {%2,%3,%4,%5}, {%6,%7}, {%0,%1};"
        : "+r"(d[0]), "+r"(d[1])
        : "r"(a[0]), "r"(a[1]), "r"(a[2]), "r"(a[3]), "r"(b0), "r"(b1));
}
// cp.async 128 rows x 64 half (128B rows), SW swizzle; 256 threads.
__device__ __forceinline__ void cp_tile(u32 sdst, const half* g, int ld, int tid) {
    const int seg = tid & 7;
    const int r0 = tid >> 3;
    const char* gc = (const char*)g + seg * 16;
#pragma unroll
    for (int p = 0; p < 4; p++) {
        int row = p * 32 + r0;
        u32 dst = sdst + row * 128 + ((seg ^ (row & 7)) << 4);
        const void* src = gc + (size_t)row * ld * sizeof(half);
        asm volatile("cp.async.cg.shared.global [%0], [%1], 16;" :: "r"(dst), "l"(src) : "memory");
    }
}
// cp.async 64 rows x 128 half (256B rows); 256 threads.
__device__ __forceinline__ void cp_tileB(u32 sdst, const half* g, int ld, int tid) {
    const int seg = tid & 15;
    const int r0 = tid >> 4;
    const char* gc = (const char*)g + seg * 16;
#pragma unroll
    for (int p = 0; p < 4; p++) {
        int row = p * 16 + r0;
        u32 dst = sdst + row * 256 + ((seg ^ (row & 7)) << 4);
        const void* src = gc + (size_t)row * ld * sizeof(half);
        asm volatile("cp.async.cg.shared.global [%0], [%1], 16;" :: "r"(dst), "l"(src) : "memory");
    }
}

// ---------------------------------------------------------------------------
// GEMM D[m,n] = scale*(A.B) + bias; fp16 2-term split.
// NPROD=3: AhBh (f32 acc) + AlBh + AhBl (f16 acc — cross terms are tiny,
//   ~3e-4 of the main term, so fp16 accumulation adds ~1e-6 relative error
//   while running at 2x HMMA rate).
// NPROD=1: AhBh only.
// BM=128, BN=128, BK=64. 8 warps (4M x 2N). 2-stage cp.async.
// BTRANS: B is [k][n] n-contig via ldmatrix.trans. TRI: triangular G grid.
// ---------------------------------------------------------------------------
template <bool BIASROW, bool SPLIT, int KSPL, bool TRI, bool BTRANS, int NPROD>
__global__ __launch_bounds__(256) void gemm_mma(
    const half* __restrict__ Ah, const half* __restrict__ Al, size_t sA, int lda,
    const half* __restrict__ Bh, const half* __restrict__ Bl, size_t sB, int ldb,
    float* __restrict__ C, half* __restrict__ Ch, half* __restrict__ Cl,
    size_t sC, int ldc, const float* __restrict__ bias, int biasZ,
    float scale, int K)
{
    constexpr u32 NA = (NPROD >= 2) ? 2 : 1;
    constexpr u32 NB = (NPROD == 3) ? 2 : 1;
    constexpr u32 STAGE = NA * 16384 + NB * 16384;

    extern __shared__ char dyn[];
    char* dg = (char*)(((size_t)dyn + 1023) & ~(size_t)1023);
    const u32 base = smem_u32(dg);

    const int tid = threadIdx.x, wid = tid >> 5, lane = tid & 31;
    const int z = blockIdx.z;
    const int batch = z / KSPL, ksl = z - batch * KSPL;
    const int m0 = TRI ? c_ti[blockIdx.x] * 128 : blockIdx.y * 128;
    const int n0 = TRI ? c_tj[blockIdx.x] * 128 : blockIdx.x * 128;
    const int wm = wid & 3, wn = wid >> 2;

    const half* pAh = Ah + (size_t)batch * sA + (size_t)ksl * K + (size_t)m0 * lda;
    const half* pAl = Al + (size_t)batch * sA + (size_t)ksl * K + (size_t)m0 * lda;
    const half* pBh;
    const half* pBl;
    if (BTRANS) {
        pBh = Bh + (size_t)batch * sB + (size_t)(ksl * K) * ldb + n0;
        pBl = Bl + (size_t)batch * sB + (size_t)(ksl * K) * ldb + n0;
    } else {
        pBh = Bh + (size_t)batch * sB + (size_t)ksl * K + (size_t)n0 * ldb;
        pBl = Bl + (size_t)batch * sB + (size_t)ksl * K + (size_t)n0 * ldb;
    }

    const int NCH = K >> 6;

    float acc[2][8][4];
#pragma unroll
    for (int i = 0; i < 2; i++)
#pragma unroll
        for (int j = 0; j < 8; j++)
#pragma unroll
            for (int t = 0; t < 4; t++) acc[i][j][t] = 0.0f;

    // fp16 cross-term accumulators (only used when NPROD==3)
    u32 acc16[2][8][2];
    if (NPROD == 3) {
#pragma unroll
        for (int i = 0; i < 2; i++)
#pragma unroll
            for (int j = 0; j < 8; j++) { acc16[i][j][0] = 0; acc16[i][j][1] = 0; }
    }

    // prologue
    cp_tile(base, pAh, lda, tid);
    if (NPROD >= 2) cp_tile(base + 16384, pAl, lda, tid);
    const u32 bofs = NA * 16384;
    if (BTRANS) {
        cp_tileB(base + bofs, pBh, ldb, tid);
        if (NPROD == 3) cp_tileB(base + bofs + 16384, pBl, ldb, tid);
    } else {
        cp_tile(base + bofs, pBh, ldb, tid);
        if (NPROD == 3) cp_tile(base + bofs + 16384, pBl, ldb, tid);
    }
    asm volatile("cp.async.commit_group;" ::: "memory");

    for (int c = 0; c < NCH; c++) {
        const int st = c & 1;
        if (c + 1 < NCH) {
            const u32 sb = base + (st ^ 1) * STAGE;
            const int ko = (c + 1) * 64;
            cp_tile(sb, pAh + ko, lda, tid);
            if (NPROD >= 2) cp_tile(sb + 16384, pAl + ko, lda, tid);
            if (BTRANS) {
                cp_tileB(sb + bofs, pBh + (size_t)ko * ldb, ldb, tid);
                if (NPROD == 3) cp_tileB(sb + bofs + 16384, pBl + (size_t)ko * ldb, ldb, tid);
            } else {
                cp_tile(sb + bofs, pBh + ko, ldb, tid);
                if (NPROD == 3) cp_tile(sb + bofs + 16384, pBl + ko, ldb, tid);
            }
        }
        asm volatile("cp.async.commit_group;" ::: "memory");
        asm volatile("cp.async.wait_group 1;" ::: "memory");
        __syncthreads();

        const u32 sAh = base + st * STAGE;
        const u32 sAl = sAh + 16384;
        const u32 sBh = sAh + bofs, sBl = sAh + bofs + 16384;

#pragma unroll
        for (int ks = 0; ks < 4; ks++) {
            u32 ah[2][4], al[2][4];
#pragma unroll
            for (int mi = 0; mi < 2; mi++) {
                const int row = wm * 32 + mi * 16 + (lane & 15);
                const u32 off = row * 128 + ((((ks << 1) | (lane >> 4)) ^ (row & 7)) << 4);
                ldsm4(ah[mi][0], ah[mi][1], ah[mi][2], ah[mi][3], sAh + off);
                if (NPROD >= 2)
                    ldsm4(al[mi][0], al[mi][1], al[mi][2], al[mi][3], sAl + off);
            }
            u32 bh[4][4], bl[4][4];
#pragma unroll
            for (int ni = 0; ni < 4; ni++) {
                if (BTRANS) {
                    const int row = ks * 16 + (lane & 15);
                    const int chunk = wn * 8 + ni * 2 + (lane >> 4);
                    const u32 off = row * 256 + ((chunk ^ (row & 7)) << 4);
                    ldsm4t(bh[ni][0], bh[ni][1], bh[ni][2], bh[ni][3], sBh + off);
                    if (NPROD == 3) ldsm4t(bl[ni][0], bl[ni][1], bl[ni][2], bl[ni][3], sBl + off);
                } else {
                    const int row = wn * 64 + ni * 16 + (lane & 15);
                    const u32 off = row * 128 + ((((ks << 1) | (lane >> 4)) ^ (row & 7)) << 4);
                    ldsm4(bh[ni][0], bh[ni][1], bh[ni][2], bh[ni][3], sBh + off);
                    if (NPROD == 3) ldsm4(bl[ni][0], bl[ni][1], bl[ni][2], bl[ni][3], sBl + off);
                }
            }
            const int p0 = BTRANS ? 1 : 2;   // k-hi fragment index
            const int q0 = BTRANS ? 2 : 1;   // n+8 fragment base
            // main product: fp32 accumulate
#pragma unroll
            for (int mi = 0; mi < 2; mi++)
#pragma unroll
                for (int ni = 0; ni < 4; ni++) {
                    mma16816(acc[mi][2 * ni + 0], ah[mi], bh[ni][0], bh[ni][p0]);
                    mma16816(acc[mi][2 * ni + 1], ah[mi], bh[ni][q0], bh[ni][3]);
                }
            // cross products: fp16 accumulate (2x rate)
            if (NPROD == 3) {
#pragma unroll
                for (int mi = 0; mi < 2; mi++)
#pragma unroll
                    for (int ni = 0; ni < 4; ni++) {
                        mma16816h(acc16[mi][2 * ni + 0], al[mi], bh[ni][0], bh[ni][p0]);
                        mma16816h(acc16[mi][2 * ni + 1], al[mi], bh[ni][q0], bh[ni][3]);
                        mma16816h(acc16[mi][2 * ni + 0], ah[mi], bl[ni][0], bl[ni][p0]);
                        mma16816h(acc16[mi][2 * ni + 1], ah[mi], bl[ni][q0], bl[ni][3]);
                    }
            }
        }
        __syncthreads();
    }

    // epilogue
    const int mwarp = m0 + wm * 32;
    const int nwarp = n0 + wn * 64;
#pragma unroll
    for (int mi = 0; mi < 2; mi++) {
        const int r0 = mwarp + mi * 16 + (lane >> 2);
        float br0 = 0.f, br1 = 0.f;
        if (BIASROW) { br0 = bias[z * biasZ + r0]; br1 = bias[z * biasZ + r0 + 8]; }
#pragma unroll
        for (int nj = 0; nj < 8; nj++) {
            const int col = nwarp + nj * 8 + (lane & 3) * 2;
            const float* d = acc[mi][nj];
            float e00 = 0.f, e01 = 0.f, e10 = 0.f, e11 = 0.f;
            if (NPROD == 3) {
                float2 lo = unpack2h(acc16[mi][nj][0]);
                float2 hi = unpack2h(acc16[mi][nj][1]);
                e00 = lo.x; e01 = lo.y; e10 = hi.x; e11 = hi.y;
            }
            float v00 = (d[0] + e00) * scale + br0;
            float v01 = (d[1] + e01) * scale + br0;
            float v10 = (d[2] + e10) * scale + br1;
            float v11 = (d[3] + e11) * scale + br1;
            const size_t i0 = (size_t)z * sC + (size_t)r0 * ldc + col;
            const size_t i1 = i0 + (size_t)8 * ldc;
            if (SPLIT) {
                if (Cl) {
                    u32 h, l;
                    split2h(v00, v01, h, l);
                    *(u32*)(Ch + i0) = h; *(u32*)(Cl + i0) = l;
                    split2h(v10, v11, h, l);
                    *(u32*)(Ch + i1) = h; *(u32*)(Cl + i1) = l;
                } else {
                    u32 h;
                    pack2h(v00, v01, h); *(u32*)(Ch + i0) = h;
                    pack2h(v10, v11, h); *(u32*)(Ch + i1) = h;
                }
            } else {
                *(float2*)(C + i0) = make_float2(v00, v01);
                *(float2*)(C + i1) = make_float2(v10, v11);
            }
        }
    }
}

// ---------------- elementwise kernels ----------------
__global__ void xsplit_sum(const float* __restrict__ x, half* __restrict__ xh,
                           half* __restrict__ xl, float* __restrict__ sx)
{
    const int r = blockIdx.x, tid = threadIdx.x;
    const float4* in = (const float4*)(x + (size_t)r * TT);
    uint2* oh = (uint2*)(xh + (size_t)r * TT);
    uint2* ol = (uint2*)(xl + (size_t)r * TT);
    float sum = 0.f;
#pragma unroll
    for (int i = 0; i < 4; i++) {
        const int idx = tid + i * 256;
        float4 v = in[idx];
        sum += v.x + v.y + v.z + v.w;
        uint2 h, l;
        split2h(v.x, v.y, h.x, l.x);
        split2h(v.z, v.w, h.y, l.y);
        oh[idx] = h;
        ol[idx] = l;
    }
#pragma unroll
    for (int o = 16; o > 0; o >>= 1) sum += __shfl_xor_sync(~0u, sum, o);
    __shared__ float red[8];
    if ((tid & 31) == 0) red[tid >> 5] = sum;
    __syncthreads();
    if (tid == 0) {
        float t = 0.f;
#pragma unroll
        for (int i = 0; i < 8; i++) t += red[i];
        sx[r] = t;
    }
}

__global__ void esplit3(const float* __restrict__ w0, const float* __restrict__ w1,
                        const float* __restrict__ w2, half* __restrict__ oh0,
                        half* __restrict__ ol0, half* __restrict__ oh1,
                        half* __restrict__ ol1, half* __restrict__ oh2,
                        half* __restrict__ ol2)
{
    const int which = blockIdx.y;
    const float* in = which == 0 ? w0 : (which == 1 ? w1 : w2);
    half* oh = which == 0 ? oh0 : (which == 1 ? oh1 : oh2);
    half* ol = which == 0 ? ol0 : (which == 1 ? ol1 : ol2);
    size_t i = ((size_t)blockIdx.x * blockDim.x + threadIdx.x) * 4;
    float4 v = *(const float4*)(in + i);
    uint2 h, l;
    split2h(v.x, v.y, h.x, l.x);
    split2h(v.z, v.w, h.y, l.y);
    *(uint2*)(oh + i) = h;
    *(uint2*)(ol + i) = l;
}

__global__ void gcombine_sym(const float* __restrict__ part, half* __restrict__ gh,
                             half* __restrict__ gl)
{
    __shared__ float t[32][33];
    const int ti = c_ti[blockIdx.y], tj = c_tj[blockIdx.y];
    const int sxo = (blockIdx.x & 3) * 32, syo = (blockIdx.x >> 2) * 32;
    const int b = blockIdx.z;
    const int r0 = ti * 128 + syo, c0 = tj * 128 + sxo;
    const int tx = threadIdx.x, ty = threadIdx.y;
    const float* pz = part + (size_t)b * KSPL_G * CCSQ;
    half* ghb = gh + (size_t)b * CCSQ;
    half* glb = gl + (size_t)b * CCSQ;
#pragma unroll
    for (int p = 0; p < 4; p++) {
        const int r = r0 + ty + p * 8;
        const size_t w = (size_t)r * CC + c0 + tx;
        float s = pz[w] + pz[w + CCSQ] + pz[w + 2 * CCSQ] + pz[w + 3 * CCSQ];
        t[ty + p * 8][tx] = s;
        __half h = __float2half_rn(s);
        ghb[w] = h;
        glb[w] = __float2half_rn(s - __half2float(h));
    }
    if (ti != tj) {
        __syncthreads();
#pragma unroll
        for (int p = 0; p < 4; p++) {
            float s = t[tx][ty + p * 8];
            const size_t w = (size_t)(c0 + ty + p * 8) * CC + r0 + tx;
            __half h = __float2half_rn(s);
            ghb[w] = h;
            glb[w] = __float2half_rn(s - __half2float(h));
        }
    }
}

__global__ void matvec_w(const float* __restrict__ Wq, const float* __restrict__ Wk,
                         const float* __restrict__ sx, float* __restrict__ w1,
                         float* __restrict__ w2)
{
    const int w = threadIdx.x >> 5, lane = threadIdx.x & 31;
    const int c = blockIdx.x * 8 + w, b = blockIdx.z;
    const float* W = blockIdx.y ? Wk : Wq;
    float* outp = blockIdx.y ? w2 : w1;
    const float4* Wr = (const float4*)(W + (size_t)c * CC);
    const float4* sv = (const float4*)(sx + b * CC);
    float s = 0.f;
#pragma unroll
    for (int i = 0; i < 4; i++) {
        float4 a = Wr[lane + 32 * i], xv = sv[lane + 32 * i];
        s += a.x * xv.x + a.y * xv.y + a.z * xv.z + a.w * xv.w;
    }
#pragma unroll
    for (int o = 16; o > 0; o >>= 1) s += __shfl_xor_sync(~0u, s, o);
    if (lane == 0) outp[b * CC + c] = s;
}

// softmax + rank-1 corrections + pb = attn*bv; writes attn hi only
__global__ void softmax_corr(const float* __restrict__ d, const float* __restrict__ w1,
                             const float* __restrict__ w2, const float* __restrict__ bq,
                             const float* __restrict__ bk, const float* __restrict__ bv,
                             half* __restrict__ ah, float* __restrict__ pb)
{
    const int gw = (blockIdx.x * blockDim.x + threadIdx.x) >> 5;
    const int lane = threadIdx.x & 31;
    const int b = gw >> 9, c = gw & 511;
    const float bqc = bq[c], w1c = w1[b * CC + c];
    const float4* r = (const float4*)(d + (size_t)gw * CC);
    const float4* w2r = (const float4*)(w2 + b * CC);
    const float4* bkr = (const float4*)bk;
    const float4* bvr = (const float4*)bv;

    float4 v[4], bvv[4];
    float mx = -1e30f;
#pragma unroll
    for (int i = 0; i < 4; i++) {
        const int idx = lane + 32 * i;
        float4 dv = r[idx], w2v = w2r[idx], bkv = bkr[idx];
        bvv[i] = bvr[idx];
        v[i].x = dv.x + SCALE_F * (bqc * (w2v.x + (float)TT * bkv.x) + w1c * bkv.x);
        v[i].y = dv.y + SCALE_F * (bqc * (w2v.y + (float)TT * bkv.y) + w1c * bkv.y);
        v[i].z = dv.z + SCALE_F * (bqc * (w2v.z + (float)TT * bkv.z) + w1c * bkv.z);
        v[i].w = dv.w + SCALE_F * (bqc * (w2v.w + (float)TT * bkv.w) + w1c * bkv.w);
        mx = fmaxf(mx, fmaxf(fmaxf(v[i].x, v[i].y), fmaxf(v[i].z, v[i].w)));
    }
#pragma unroll
    for (int o = 16; o > 0; o >>= 1) mx = fmaxf(mx, __shfl_xor_sync(~0u, mx, o));
    float s = 0.f;
#pragma unroll
    for (int i = 0; i < 4; i++) {
        v[i].x = expf(v[i].x - mx); v[i].y = expf(v[i].y - mx);
        v[i].z = expf(v[i].z - mx); v[i].w = expf(v[i].w - mx);
        s += v[i].x + v[i].y + v[i].z + v[i].w;
    }
#pragma unroll
    for (int o = 16; o > 0; o >>= 1) s += __shfl_xor_sync(~0u, s, o);
    const float inv = 1.0f / s;
    float dotbv = 0.f;
#pragma unroll
    for (int i = 0; i < 4; i++) {
        v[i].x *= inv; v[i].y *= inv; v[i].z *= inv; v[i].w *= inv;
        dotbv += v[i].x * bvv[i].x + v[i].y * bvv[i].y + v[i].z * bvv[i].z + v[i].w * bvv[i].w;
        uint2 h;
        pack2h(v[i].x, v[i].y, h.x);
        pack2h(v[i].z, v[i].w, h.y);
        size_t o = (size_t)gw * CC + 4 * (lane + 32 * i);
        *(uint2*)(ah + o) = h;
    }
#pragma unroll
    for (int o = 16; o > 0; o >>= 1) dotbv += __shfl_xor_sync(~0u, dotbv, o);
    if (lane == 0) pb[gw] = dotbv;
}

// ---------------- launch ----------------
extern "C" void kernel_launch(void* const* d_in, const int* in_sizes, int n_in,
                              void* d_out, int out_size)
{
    (void)in_sizes; (void)n_in; (void)out_size;
    const float* x  = (const float*)d_in[0];
    const float* Wq = (const float*)d_in[1];
    const float* bq = (const float*)d_in[2];
    const float* Wk = (const float*)d_in[3];
    const float* bk = (const float*)d_in[4];
    const float* Wv = (const float*)d_in[5];
    const float* bv = (const float*)d_in[6];
    float* out = (float*)d_out;

    half *xh, *xl, *wqh, *wql, *wkh, *wkl, *wvh, *wvl;
    half *Gh, *Gl, *t2h, *t2l, *aH, *Ph, *Pl;
    float *part, *dots, *sx, *w1, *w2, *pb;
    cudaGetSymbolAddress((void**)&xh, g_x_h);
    cudaGetSymbolAddress((void**)&xl, g_x_l);
    cudaGetSymbolAddress((void**)&wqh, g_wq_h);
    cudaGetSymbolAddress((void**)&wql, g_wq_l);
    cudaGetSymbolAddress((void**)&wkh, g_wk_h);
    cudaGetSymbolAddress((void**)&wkl, g_wk_l);
    cudaGetSymbolAddress((void**)&wvh, g_wv_h);
    cudaGetSymbolAddress((void**)&wvl, g_wv_l);
    cudaGetSymbolAddress((void**)&part, g_part);
    cudaGetSymbolAddress((void**)&Gh, g_G_h);
    cudaGetSymbolAddress((void**)&Gl, g_G_l);
    cudaGetSymbolAddress((void**)&t2h, g_t2_h);
    cudaGetSymbolAddress((void**)&t2l, g_t2_l);
    cudaGetSymbolAddress((void**)&dots, g_dots);
    cudaGetSymbolAddress((void**)&aH, g_a_h);
    cudaGetSymbolAddress((void**)&Ph, g_P_h);
    cudaGetSymbolAddress((void**)&Pl, g_P_l);
    cudaGetSymbolAddress((void**)&sx, g_sx);
    cudaGetSymbolAddress((void**)&w1, g_w1);
    cudaGetSymbolAddress((void**)&w2, g_w2);
    cudaGetSymbolAddress((void**)&pb, g_pb);

    const size_t CT = (size_t)CC * TT;
    const int SM_3 = 2 * (2 * 16384 + 2 * 16384) + 1024;  // NPROD=3: 132096
    const int SM_1 = 2 * (16384 + 16384) + 1024;          // NPROD=1: 66560

    cudaFuncSetAttribute(gemm_mma<false, false, KSPL_G, true, false, 3>, cudaFuncAttributeMaxDynamicSharedMemorySize, SM_3);
    cudaFuncSetAttribute(gemm_mma<false, true, 1, false, false, 3>, cudaFuncAttributeMaxDynamicSharedMemorySize, SM_3);
    cudaFuncSetAttribute(gemm_mma<false, false, 1, false, false, 3>, cudaFuncAttributeMaxDynamicSharedMemorySize, SM_3);
    cudaFuncSetAttribute(gemm_mma<false, true, 1, false, true, 1>, cudaFuncAttributeMaxDynamicSharedMemorySize, SM_1);
    cudaFuncSetAttribute(gemm_mma<true, false, 1, false, true, 1>, cudaFuncAttributeMaxDynamicSharedMemorySize, SM_1);

    // prep
    xsplit_sum<<<BB * CC, 256>>>(x, xh, xl, sx);
    esplit3<<<dim3(CCSQ / 1024, 3), 256>>>(Wq, Wk, Wv, wqh, wql, wkh, wkl, wvh, wvl);
    matvec_w<<<dim3(CC / 8, 2, BB), 256>>>(Wq, Wk, sx, w1, w2);

    // G = x x^T : upper-triangle 128-tiles, split-K x4 partials
    gemm_mma<false, false, KSPL_G, true, false, 3><<<dim3(10, 1, BB * KSPL_G), 256, SM_3>>>(
        xh, xl, CT, TT, xh, xl, CT, TT, part, nullptr, nullptr,
        CCSQ, CC, nullptr, 0, 1.0f, TT / KSPL_G);
    gcombine_sym<<<dim3(16, 10, BB), dim3(32, 8)>>>(part, Gh, Gl);

    // t2 = Wq * G
    gemm_mma<false, true, 1, false, false, 3><<<dim3(4, 4, BB), 256, SM_3>>>(
        wqh, wql, 0, CC, Gh, Gl, CCSQ, CC, nullptr, t2h, t2l,
        CCSQ, CC, nullptr, 0, 1.0f, CC);
    // dots = SCALE * t2 * Wk^T
    gemm_mma<false, false, 1, false, false, 3><<<dim3(4, 4, BB), 256, SM_3>>>(
        t2h, t2l, CCSQ, CC, wkh, wkl, 0, CC, dots, nullptr, nullptr,
        CCSQ, CC, nullptr, 0, SCALE_F, CC);
    // softmax + corrections + pb (attn hi only)
    softmax_corr<<<BB * CC / 4, 128>>>(dots, w1, w2, bq, bk, bv, aH, pb);
    // P = aH * Wv (1-product; split output)
    gemm_mma<false, true, 1, false, true, 1><<<dim3(4, 4, BB), 256, SM_1>>>(
        aH, aH, CCSQ, CC, wvh, wvh, 0, CC, nullptr, Ph, Pl,
        CCSQ, CC, nullptr, 0, 1.0f, CC);
    // out = Ph * xh + pb (1-product)
    gemm_mma<true, false, 1, false, true, 1><<<dim3(TT / 128, CC / 128, BB), 256, SM_1>>>(
        Ph, Ph, CCSQ, CC, xh, xh, CT, TT, out, nullptr, nullptr,
        CT, TT, pb, CC, 1.0f, CC);
}